// round 3
// baseline (speedup 1.0000x reference)
#include <cuda_runtime.h>
#include <stdint.h>

#define B_SZ 16
#define T_SZ 8192
#define H_SZ 256
#define MTOT (B_SZ * T_SZ)   // 131072 rows

// Scratch for v = x @ W_mem^T  (allocation-free: __device__ global, 128 MiB)
__device__ float g_v[(size_t)MTOT * H_SZ];

__device__ __forceinline__ uint32_t f2tf32(float f) {
    uint32_t r;
    asm("cvt.rna.tf32.f32 %0, %1;" : "=r"(r) : "f"(f));
    return r;
}

__device__ __forceinline__ void mma_tf32(float* c, const uint32_t* a, const uint32_t* b) {
    asm volatile(
        "mma.sync.aligned.m16n8k8.row.col.f32.tf32.tf32.f32 "
        "{%0,%1,%2,%3}, {%4,%5,%6,%7}, {%8,%9}, {%0,%1,%2,%3};\n"
        : "+f"(c[0]), "+f"(c[1]), "+f"(c[2]), "+f"(c[3])
        : "r"(a[0]), "r"(a[1]), "r"(a[2]), "r"(a[3]), "r"(b[0]), "r"(b[1]));
}

#define BM 128
#define BN 128
#define BK 16
#define BKP 20   // pad: stride 20 words -> conflict-free fragment LDS, float4-aligned

// P = X @ W^T for one 128-col half of one weight.  grid = (4 n-tiles, 1024 m-tiles)
// n-tile 0,1 -> W_lin -> d_out (raw u) ; n-tile 2,3 -> W_mem -> g_v (raw v)
__global__ __launch_bounds__(256, 2)
void gemm_kernel(const float* __restrict__ X,
                 const float* __restrict__ Wlin,
                 const float* __restrict__ Wmem,
                 float* __restrict__ outU)
{
    __shared__ uint32_t As[2][BM][BKP];
    __shared__ uint32_t Bs[2][BN][BKP];

    const int ntile = blockIdx.x;                 // 0..3 (fast dim -> x tile L2 reuse)
    const int mbase = blockIdx.y * BM;
    const float* W  = (ntile < 2) ? Wlin : Wmem;
    float*      dst = (ntile < 2) ? outU : g_v;
    const int nbase = (ntile & 1) * BN;

    const int tid  = threadIdx.x;
    const int warp = tid >> 5;
    const int lane = tid & 31;
    const int wm = (warp >> 2) * 64;              // 2 warps over M
    const int wn = (warp & 3) * 32;               // 4 warps over N
    const int g  = lane >> 2;                     // groupID
    const int cq = lane & 3;                      // threadID_in_group

    // staging coords: each thread loads 2x float4 from A and B per k-tile
    const int sr = tid >> 2;                      // 0..63
    const int sc = (tid & 3) << 2;                // 0,4,8,12

    float acc[4][4][4];
    #pragma unroll
    for (int i = 0; i < 4; i++)
        #pragma unroll
        for (int j = 0; j < 4; j++)
            #pragma unroll
            for (int k = 0; k < 4; k++) acc[i][j][k] = 0.f;

    const float* Aptr = X + (size_t)mbase * H_SZ;
    const float* Bptr = W + (size_t)nbase * H_SZ;

    float4 ra[2], rb[2];
    #pragma unroll
    for (int i = 0; i < 2; i++) {
        ra[i] = *(const float4*)(Aptr + (sr + i * 64) * H_SZ + sc);
        rb[i] = *(const float4*)(Bptr + (sr + i * 64) * H_SZ + sc);
    }
    #pragma unroll
    for (int i = 0; i < 2; i++) {
        As[0][sr + i * 64][sc + 0] = f2tf32(ra[i].x);
        As[0][sr + i * 64][sc + 1] = f2tf32(ra[i].y);
        As[0][sr + i * 64][sc + 2] = f2tf32(ra[i].z);
        As[0][sr + i * 64][sc + 3] = f2tf32(ra[i].w);
        Bs[0][sr + i * 64][sc + 0] = f2tf32(rb[i].x);
        Bs[0][sr + i * 64][sc + 1] = f2tf32(rb[i].y);
        Bs[0][sr + i * 64][sc + 2] = f2tf32(rb[i].z);
        Bs[0][sr + i * 64][sc + 3] = f2tf32(rb[i].w);
    }
    __syncthreads();

    const int NK = H_SZ / BK;                     // 16
    for (int kt = 0; kt < NK; ++kt) {
        const int cur = kt & 1;
        const int nxt = cur ^ 1;
        const bool more = (kt + 1 < NK);

        if (more) {
            const int kb = (kt + 1) * BK;
            #pragma unroll
            for (int i = 0; i < 2; i++) {
                ra[i] = *(const float4*)(Aptr + (sr + i * 64) * H_SZ + kb + sc);
                rb[i] = *(const float4*)(Bptr + (sr + i * 64) * H_SZ + kb + sc);
            }
        }

        #pragma unroll
        for (int kk = 0; kk < 2; ++kk) {
            uint32_t af[4][4], bf[4][2];
            const int c0 = kk * 8 + cq;
            #pragma unroll
            for (int mi = 0; mi < 4; ++mi) {
                const int r = wm + mi * 16 + g;
                af[mi][0] = As[cur][r][c0];
                af[mi][1] = As[cur][r + 8][c0];
                af[mi][2] = As[cur][r][c0 + 4];
                af[mi][3] = As[cur][r + 8][c0 + 4];
            }
            #pragma unroll
            for (int ni = 0; ni < 4; ++ni) {
                const int r = wn + ni * 8 + g;
                bf[ni][0] = Bs[cur][r][c0];
                bf[ni][1] = Bs[cur][r][c0 + 4];
            }
            #pragma unroll
            for (int mi = 0; mi < 4; ++mi)
                #pragma unroll
                for (int ni = 0; ni < 4; ++ni)
                    mma_tf32(acc[mi][ni], af[mi], bf[ni]);
        }

        if (more) {
            #pragma unroll
            for (int i = 0; i < 2; i++) {
                As[nxt][sr + i * 64][sc + 0] = f2tf32(ra[i].x);
                As[nxt][sr + i * 64][sc + 1] = f2tf32(ra[i].y);
                As[nxt][sr + i * 64][sc + 2] = f2tf32(ra[i].z);
                As[nxt][sr + i * 64][sc + 3] = f2tf32(ra[i].w);
                Bs[nxt][sr + i * 64][sc + 0] = f2tf32(rb[i].x);
                Bs[nxt][sr + i * 64][sc + 1] = f2tf32(rb[i].y);
                Bs[nxt][sr + i * 64][sc + 2] = f2tf32(rb[i].z);
                Bs[nxt][sr + i * 64][sc + 3] = f2tf32(rb[i].w);
            }
            __syncthreads();
        }
    }

    // epilogue: c0,c1 -> (row g, cols 2cq,2cq+1), c2,c3 -> (row g+8, ...)
    #pragma unroll
    for (int mi = 0; mi < 4; ++mi) {
        const int r0 = mbase + wm + mi * 16 + g;
        #pragma unroll
        for (int ni = 0; ni < 4; ++ni) {
            const int col = nbase + wn + ni * 8 + cq * 2;
            float2 v01 = make_float2(acc[mi][ni][0], acc[mi][ni][1]);
            float2 v23 = make_float2(acc[mi][ni][2], acc[mi][ni][3]);
            *(float2*)(dst + (size_t)r0 * H_SZ + col) = v01;
            *(float2*)(dst + (size_t)(r0 + 8) * H_SZ + col) = v23;
        }
    }
}

// out[t] = u[t] + (1/count) * sum_{s=max(0,t-8)}^{t} v[s] + (b_lin + b_mem)
// CTA: 128 consecutive rows (never straddles a batch since T=8192 % 128 == 0).
// Thread: one float4 column over 32 sequential t with add/sub window recurrence.
__global__ __launch_bounds__(256)
void window_kernel(const float* __restrict__ blin,
                   const float* __restrict__ bmem,
                   float* __restrict__ out)
{
    const int tid = threadIdx.x;
    const int col = tid & 63;                     // float4 column (H/4 = 64)
    const int sub = tid >> 6;                     // 0..3
    const int rg0 = blockIdx.x * 128 + sub * 32;  // global row
    const int t0  = rg0 & (T_SZ - 1);             // t within batch

    const float4* v4 = (const float4*)g_v;
    float4* o4 = (float4*)out;

    float4 bl = ((const float4*)blin)[col];
    float4 bm = ((const float4*)bmem)[col];
    const float bx = bl.x + bm.x, by = bl.y + bm.y, bz = bl.z + bm.z, bw = bl.w + bm.w;

    float sx = 0.f, sy = 0.f, sz = 0.f, sw = 0.f;
    {
        int nprev = t0 < 8 ? t0 : 8;              // rows rg0-nprev .. rg0-1
        for (int j = 1; j <= nprev; ++j) {
            float4 v = v4[(rg0 - j) * 64 + col];
            sx += v.x; sy += v.y; sz += v.z; sw += v.w;
        }
    }

    #pragma unroll 4
    for (int i = 0; i < 32; ++i) {
        const int rg = rg0 + i;
        const int t  = t0 + i;
        float4 v = v4[rg * 64 + col];
        sx += v.x; sy += v.y; sz += v.z; sw += v.w;
        const float inv = (t >= 8) ? (1.0f / 9.0f) : (1.0f / (float)(t + 1));
        float4 u = o4[rg * 64 + col];
        float4 r;
        r.x = u.x + sx * inv + bx;
        r.y = u.y + sy * inv + by;
        r.z = u.z + sz * inv + bz;
        r.w = u.w + sw * inv + bw;
        o4[rg * 64 + col] = r;
        if (t >= 8) {
            float4 w = v4[(rg - 8) * 64 + col];
            sx -= w.x; sy -= w.y; sz -= w.z; sw -= w.w;
        }
    }
}

extern "C" void kernel_launch(void* const* d_in, const int* in_sizes, int n_in,
                              void* d_out, int out_size)
{
    const float* x    = (const float*)d_in[0];
    const float* Wlin = (const float*)d_in[1];
    const float* blin = (const float*)d_in[2];
    const float* Wmem = (const float*)d_in[3];
    const float* bmem = (const float*)d_in[4];
    float* out = (float*)d_out;

    dim3 g(4, MTOT / BM, 1);          // (n-tiles, m-tiles)
    gemm_kernel<<<g, 256>>>(x, Wlin, Wmem, out);
    window_kernel<<<MTOT / 128, 256>>>(blin, bmem, out);
}